// round 3
// baseline (speedup 1.0000x reference)
#include <cuda_runtime.h>
#include <stdint.h>

// Problem constants (fixed by reference: IM_SIZE=(1080,1920), SCALE=(0.25,0.25), B=8, C=3)
#define H_IN 1080
#define W_IN 1920
#define OH   270
#define OW   480
#define BC   24            // B*C = 8*3
#define MAX_TAPS 20        // P = ceil(16)+2 = 18 before zero-column trim

// Scratch: vertical-resized intermediate [BC, OH, W_IN] = 24*270*1920 floats (~49.8 MB)
__device__ float g_mid[(size_t)BC * OH * W_IN];

// ---------------------------------------------------------------------------
// Pass 1: vertical (H) resample.  mid[bc, oh, w] = sum_p w_h[oh,p] * x[bc, idx_h[oh,p], w]
// float4 along W (contiguous). Weights/rows staged in shared once per block.
// grid: (ceil((W/4)/128), OH, BC), block: 128
// ---------------------------------------------------------------------------
__global__ void __launch_bounds__(128)
pass1_vert(const float* __restrict__ x,
           const float* __restrict__ w_h,
           const int* __restrict__ idx_h,   // int32: JAX demotes int64 -> int32
           int taps)
{
    __shared__ float sw[MAX_TAPS];
    __shared__ int   srow[MAX_TAPS];

    const int oh = blockIdx.y;
    const int bc = blockIdx.z;
    const int t  = threadIdx.x;

    if (t < taps) {
        sw[t] = w_h[oh * taps + t];
        int r = idx_h[oh * taps + t];
        if (r < 0) r = 0;
        if (r > H_IN - 1) r = H_IN - 1;
        srow[t] = r;
    }
    __syncthreads();

    const int wq = blockIdx.x * 128 + t;        // float4 index along W
    if (wq >= W_IN / 4) return;

    const float4* xin = (const float4*)x + (size_t)bc * H_IN * (W_IN / 4) + wq;

    float4 acc = make_float4(0.f, 0.f, 0.f, 0.f);
#pragma unroll 4
    for (int p = 0; p < taps; ++p) {
        const float  w = sw[p];
        const float4 v = __ldg(xin + (size_t)srow[p] * (W_IN / 4));
        acc.x += w * v.x; acc.y += w * v.y; acc.z += w * v.z; acc.w += w * v.w;
    }

    ((float4*)g_mid)[((size_t)bc * OH + oh) * (W_IN / 4) + wq] = acc;
}

// ---------------------------------------------------------------------------
// Pass 2: horizontal (W) resample.
// out[bc, oh, ow] = sum_p w_w[ow,p] * mid[bc, oh, idx_w[ow,p]]
// Block covers a 128-wide ow chunk x ROWS_PER_BLK oh rows; weight/idx slice staged
// in shared once per block and amortized over the rows.
// grid: (ceil(OW/128), ceil(OH/ROWS_PER_BLK), BC), block: 128
// ---------------------------------------------------------------------------
#define ROWS_PER_BLK 16

__global__ void __launch_bounds__(128)
pass2_horiz(const float* __restrict__ w_w,
            const int* __restrict__ idx_w,   // int32
            float* __restrict__ out,
            int taps)
{
    __shared__ float swt[128 * MAX_TAPS];
    __shared__ int   sidx[128 * MAX_TAPS];

    const int t   = threadIdx.x;
    const int ow0 = blockIdx.x * 128;
    const int oh0 = blockIdx.y * ROWS_PER_BLK;
    const int bc  = blockIdx.z;

    // cooperative stage of this chunk's weights/indices
    const int n = 128 * taps;
    for (int i = t; i < n; i += 128) {
        const int local = i / taps;
        const int p     = i - local * taps;
        const int ow    = ow0 + local;
        if (ow < OW) {
            swt[local * taps + p] = w_w[ow * taps + p];
            int c = idx_w[ow * taps + p];
            if (c < 0) c = 0;
            if (c > W_IN - 1) c = W_IN - 1;
            sidx[local * taps + p] = c;
        }
    }
    __syncthreads();

    const int ow = ow0 + t;
    if (ow >= OW) return;

    const float* my_w   = &swt[t * taps];
    const int*   my_idx = &sidx[t * taps];

    const int oh_end = (oh0 + ROWS_PER_BLK < OH) ? oh0 + ROWS_PER_BLK : OH;
    for (int oh = oh0; oh < oh_end; ++oh) {
        const float* row = g_mid + ((size_t)bc * OH + oh) * W_IN;
        float acc = 0.f;
#pragma unroll 4
        for (int p = 0; p < taps; ++p) {
            acc += my_w[p] * __ldg(row + my_idx[p]);
        }
        out[((size_t)bc * OH + oh) * OW + ow] = acc;
    }
}

// ---------------------------------------------------------------------------
// kernel_launch
// inputs (metadata order): x(f32), w_h(f32), idx_h(i32), w_w(f32), idx_w(i32)
// output: f32 [8,3,270,480]
// ---------------------------------------------------------------------------
extern "C" void kernel_launch(void* const* d_in, const int* in_sizes, int n_in,
                              void* d_out, int out_size)
{
    const float* x     = (const float*)d_in[0];
    const float* w_h   = (const float*)d_in[1];
    const int*   idx_h = (const int*)d_in[2];
    const float* w_w   = (const float*)d_in[3];
    const int*   idx_w = (const int*)d_in[4];
    float*       out   = (float*)d_out;

    int taps_h = in_sizes[1] / OH;   // derived at runtime (expected 16 or 18)
    int taps_w = in_sizes[3] / OW;
    if (taps_h > MAX_TAPS) taps_h = MAX_TAPS;
    if (taps_w > MAX_TAPS) taps_w = MAX_TAPS;

    {
        dim3 grid((W_IN / 4 + 127) / 128, OH, BC);   // (4, 270, 24)
        pass1_vert<<<grid, 128>>>(x, w_h, idx_h, taps_h);
    }
    {
        dim3 grid((OW + 127) / 128, (OH + ROWS_PER_BLK - 1) / ROWS_PER_BLK, BC); // (4, 17, 24)
        pass2_horiz<<<grid, 128>>>(w_w, idx_w, out, taps_w);
    }
}

// round 4
// speedup vs baseline: 2.7313x; 2.7313x over previous
#include <cuda_runtime.h>
#include <stdint.h>

// Problem constants (fixed: IM_SIZE=(1080,1920), SCALE=(0.25,0.25), B=8, C=3)
#define H_IN 1080
#define W_IN 1920
#define OH   270
#define OW   480
#define BC   24
#define MAX_TAPS 20

// Scratch: vertical-resized intermediate [BC, OH, W_IN] (~49.8 MB)
__device__ float g_mid[(size_t)BC * OH * W_IN];

// ---------------------------------------------------------------------------
// Pass 1: vertical resample. mid[bc,oh,w] = sum_p w_h[oh,p] * x[bc, idx_h[oh,p], w]
// float4 along W; weights/rows staged in shared once per block.
// ---------------------------------------------------------------------------
template <int TAPS>
__global__ void __launch_bounds__(128)
pass1_vert(const float* __restrict__ x,
           const float* __restrict__ w_h,
           const int* __restrict__ idx_h,
           int taps_rt)
{
    const int taps = (TAPS > 0) ? TAPS : taps_rt;
    __shared__ float sw[MAX_TAPS];
    __shared__ int   srow[MAX_TAPS];

    const int oh = blockIdx.y;
    const int bc = blockIdx.z;
    const int t  = threadIdx.x;

    if (t < taps) {
        sw[t] = w_h[oh * taps + t];
        int r = idx_h[oh * taps + t];
        r = (r < 0) ? 0 : (r > H_IN - 1 ? H_IN - 1 : r);
        srow[t] = r;
    }
    __syncthreads();

    const int wq = blockIdx.x * 128 + t;
    if (wq >= W_IN / 4) return;

    const float4* xin = (const float4*)x + (size_t)bc * H_IN * (W_IN / 4) + wq;

    float4 acc = make_float4(0.f, 0.f, 0.f, 0.f);
#pragma unroll
    for (int p = 0; p < ((TAPS > 0) ? TAPS : MAX_TAPS); ++p) {
        if (TAPS == 0 && p >= taps) break;
        const float  w = sw[p];
        const float4 v = __ldg(xin + (size_t)srow[p] * (W_IN / 4));
        acc.x += w * v.x; acc.y += w * v.y; acc.z += w * v.z; acc.w += w * v.w;
    }

    ((float4*)g_mid)[((size_t)bc * OH + oh) * (W_IN / 4) + wq] = acc;
}

// ---------------------------------------------------------------------------
// Pass 2: horizontal resample via smem-staged row gather.
// Block = 480 threads (one ow each), R rows of oh. Stage full mid row into
// skewed smem (pos = c + c/32 -> conflict-free stride-4 gather), gather taps
// from registerized weight/idx tables.
// grid: (1, ceil(OH/R), BC), block: 480
// ---------------------------------------------------------------------------
#define R_ROWS 8
#define SROW_SZ (W_IN + W_IN / 32)   // 1980 floats, skewed

template <int TAPS>
__global__ void __launch_bounds__(480)
pass2_horiz(const float* __restrict__ w_w,
            const int* __restrict__ idx_w,
            float* __restrict__ out,
            int taps_rt)
{
    const int taps = (TAPS > 0) ? TAPS : taps_rt;
    __shared__ float srow[SROW_SZ];

    const int t   = threadIdx.x;     // == ow (OW == 480)
    const int bc  = blockIdx.z;
    const int oh0 = blockIdx.y * R_ROWS;

    // Per-thread weights + pre-skewed smem positions (registers)
    float wreg[(TAPS > 0) ? TAPS : MAX_TAPS];
    int   preg[(TAPS > 0) ? TAPS : MAX_TAPS];
#pragma unroll
    for (int p = 0; p < ((TAPS > 0) ? TAPS : MAX_TAPS); ++p) {
        if (TAPS == 0 && p >= taps) break;
        wreg[p] = w_w[t * taps + p];
        int c = idx_w[t * taps + p];
        c = (c < 0) ? 0 : (c > W_IN - 1 ? W_IN - 1 : c);
        preg[p] = c + (c >> 5);
    }

    const int c0   = t * 4;
    const int base = c0 + (c0 >> 5);   // c0 % 32 <= 28, so 4 floats stay in one group

    for (int r = 0; r < R_ROWS; ++r) {
        const int oh = oh0 + r;
        if (oh >= OH) break;           // uniform across block

        // Stage: 480 coalesced float4 loads -> skewed smem
        const float4* row4 = (const float4*)g_mid + ((size_t)bc * OH + oh) * (W_IN / 4);
        float4 v = __ldg(row4 + t);
        srow[base + 0] = v.x;
        srow[base + 1] = v.y;
        srow[base + 2] = v.z;
        srow[base + 3] = v.w;
        __syncthreads();

        float acc = 0.f;
#pragma unroll
        for (int p = 0; p < ((TAPS > 0) ? TAPS : MAX_TAPS); ++p) {
            if (TAPS == 0 && p >= taps) break;
            acc += wreg[p] * srow[preg[p]];
        }
        out[((size_t)bc * OH + oh) * OW + t] = acc;
        __syncthreads();
    }
}

// ---------------------------------------------------------------------------
// kernel_launch
// inputs: x(f32), w_h(f32), idx_h(i32), w_w(f32), idx_w(i32); output f32
// ---------------------------------------------------------------------------
extern "C" void kernel_launch(void* const* d_in, const int* in_sizes, int n_in,
                              void* d_out, int out_size)
{
    const float* x     = (const float*)d_in[0];
    const float* w_h   = (const float*)d_in[1];
    const int*   idx_h = (const int*)d_in[2];
    const float* w_w   = (const float*)d_in[3];
    const int*   idx_w = (const int*)d_in[4];
    float*       out   = (float*)d_out;

    int taps_h = in_sizes[1] / OH;
    int taps_w = in_sizes[3] / OW;
    if (taps_h > MAX_TAPS) taps_h = MAX_TAPS;
    if (taps_w > MAX_TAPS) taps_w = MAX_TAPS;

    {
        dim3 grid((W_IN / 4 + 127) / 128, OH, BC);   // (4, 270, 24)
        if (taps_h == 16)
            pass1_vert<16><<<grid, 128>>>(x, w_h, idx_h, taps_h);
        else
            pass1_vert<0><<<grid, 128>>>(x, w_h, idx_h, taps_h);
    }
    {
        dim3 grid(1, (OH + R_ROWS - 1) / R_ROWS, BC); // (1, 34, 24)
        if (taps_w == 16)
            pass2_horiz<16><<<grid, 480>>>(w_w, idx_w, out, taps_w);
        else
            pass2_horiz<0><<<grid, 480>>>(w_w, idx_w, out, taps_w);
    }
}